// round 7
// baseline (speedup 1.0000x reference)
#include <cuda_runtime.h>
#include <math.h>

#define NN 100000
#define EE 1600000
#define DD 128
#define CC 47

// ---------------- scratch (device globals, no allocation) ----------------
__device__ int   g_deg[NN];
__device__ int   g_rowstart[NN + 1];
__device__ int   g_cursor[NN];
__device__ int   g_csrsrc[EE];
__device__ float g_agg[(size_t)NN * DD];
__device__ float g_b0[(size_t)NN * DD];
__device__ float g_b1[(size_t)NN * DD];
__device__ float g_stats[2 * DD];
__device__ int   g_is64;

// ---------------- edge dtype probe ----------------
// If edge_index is int64 with values < 2^31, every odd 32-bit word is 0.
// If it's int32, odd words are ordinary indices (overwhelmingly nonzero).
__global__ void probe_kernel(const int* __restrict__ ei32) {
    if (threadIdx.x == 0) {
        int nz = 0;
        for (int i = 0; i < 512; i++) nz += (ei32[2 * i + 1] != 0);
        g_is64 = (nz == 0) ? 1 : 0;
    }
}

__device__ __forceinline__ int edge_val(const void* ei, int is64, size_t idx) {
    if (is64) return (int)((const long long*)ei)[idx];
    return ((const int*)ei)[idx];
}

// ---------------- CSR build ----------------
__global__ void zero_deg_kernel() {
    int i = blockIdx.x * blockDim.x + threadIdx.x;
    if (i < NN) g_deg[i] = 0;
}

__global__ void deg_kernel(const void* __restrict__ ei) {
    int e = blockIdx.x * blockDim.x + threadIdx.x;
    int is64 = g_is64;
    if (e < EE) {
        int d = edge_val(ei, is64, (size_t)EE + e);
        atomicAdd(&g_deg[d], 1);
    }
}

// single-block chunked exclusive scan: deg -> rowstart (+ cursor copy)
__global__ void scan_kernel() {
    __shared__ int sdata[1024];
    __shared__ int carry;
    int tid = threadIdx.x;
    if (tid == 0) carry = 0;
    __syncthreads();
    for (int base = 0; base < NN; base += 1024) {
        int i = base + tid;
        int v = (i < NN) ? g_deg[i] : 0;
        sdata[tid] = v;
        __syncthreads();
#pragma unroll
        for (int off = 1; off < 1024; off <<= 1) {
            int t = (tid >= off) ? sdata[tid - off] : 0;
            __syncthreads();
            sdata[tid] += t;
            __syncthreads();
        }
        int incl = sdata[tid];
        int excl = incl - v + carry;
        if (i < NN) {
            g_rowstart[i] = excl;
            g_cursor[i] = excl;
        }
        __syncthreads();
        if (tid == 1023) carry += sdata[1023];
        __syncthreads();
    }
    if (tid == 0) g_rowstart[NN] = EE;
}

__global__ void scatter_kernel(const void* __restrict__ ei) {
    int e = blockIdx.x * blockDim.x + threadIdx.x;
    int is64 = g_is64;
    if (e < EE) {
        int d = edge_val(ei, is64, (size_t)EE + e);
        int s = edge_val(ei, is64, (size_t)e);
        int p = atomicAdd(&g_cursor[d], 1);
        g_csrsrc[p] = s;
    }
}

// ---------------- mean aggregation: warp per node ----------------
__global__ void agg_kernel(const float* __restrict__ X, float* __restrict__ AGG) {
    int warp = (blockIdx.x * blockDim.x + threadIdx.x) >> 5;
    int lane = threadIdx.x & 31;
    if (warp >= NN) return;
    int beg = g_rowstart[warp];
    int end = g_rowstart[warp + 1];
    float4 acc = make_float4(0.f, 0.f, 0.f, 0.f);
    for (int e = beg; e < end; e++) {
        int s = g_csrsrc[e];
        float4 v = *reinterpret_cast<const float4*>(X + (size_t)s * DD + lane * 4);
        acc.x += v.x; acc.y += v.y; acc.z += v.z; acc.w += v.w;
    }
    int cnt = end - beg;
    float inv = 1.0f / (float)(cnt > 0 ? cnt : 1);
    acc.x *= inv; acc.y *= inv; acc.z *= inv; acc.w *= inv;
    *reinterpret_cast<float4*>(AGG + (size_t)warp * DD + lane * 4) = acc;
}

// ---------------- fused GEMM: Y = AGG@Wl + X@Wr + bias ----------------
// K = 256 logical (first 128 from AGG via Wl, next 128 from X via Wr).
// tile 64x64, BK=16, 256 threads, 4x4 per thread.
template <int NOUT>
__global__ void gemm_kernel(const float* __restrict__ A, const float* __restrict__ X,
                            const float* __restrict__ Wl, const float* __restrict__ Wr,
                            const float* __restrict__ bias, float* __restrict__ Y) {
    __shared__ float As[16][68];   // transposed; row stride 272B = 17*16B (float4-safe)
    __shared__ float Bs[16][64];
    int tid = threadIdx.x;
    int tx = tid & 15;
    int ty = tid >> 4;
    int nbase = blockIdx.y * 64;
    int cbase = blockIdx.x * 64;

    int lm  = tid >> 2;        // 0..63 : A row
    int lk4 = (tid & 3) * 4;   // 0..12 : A k offset (float4)
    int bk  = tid >> 4;        // 0..15 : B k row
    int bc  = (tid & 15) * 4;  // 0..60 : B col offset

    float acc[4][4];
#pragma unroll
    for (int i = 0; i < 4; i++)
#pragma unroll
        for (int j = 0; j < 4; j++) acc[i][j] = 0.f;

#pragma unroll 1
    for (int kt = 0; kt < 16; kt++) {
        const float* Asrc = (kt < 8) ? A : X;
        const float* Wsrc = (kt < 8) ? Wl : Wr;
        int kofs = (kt < 8) ? kt * 16 : (kt - 8) * 16;

        int n = nbase + lm;
        float4 av = make_float4(0.f, 0.f, 0.f, 0.f);
        if (n < NN)
            av = *reinterpret_cast<const float4*>(Asrc + (size_t)n * DD + kofs + lk4);
        As[lk4 + 0][lm] = av.x;
        As[lk4 + 1][lm] = av.y;
        As[lk4 + 2][lm] = av.z;
        As[lk4 + 3][lm] = av.w;

        int krow = kofs + bk;
#pragma unroll
        for (int q = 0; q < 4; q++) {
            int c = cbase + bc + q;
            Bs[bk][bc + q] = (c < NOUT) ? Wsrc[krow * NOUT + c] : 0.f;
        }
        __syncthreads();

#pragma unroll
        for (int k = 0; k < 16; k++) {
            float4 a4 = *reinterpret_cast<const float4*>(&As[k][ty * 4]);
            float4 b4 = *reinterpret_cast<const float4*>(&Bs[k][tx * 4]);
            float a[4] = {a4.x, a4.y, a4.z, a4.w};
            float b[4] = {b4.x, b4.y, b4.z, b4.w};
#pragma unroll
            for (int i = 0; i < 4; i++)
#pragma unroll
                for (int j = 0; j < 4; j++) acc[i][j] += a[i] * b[j];
        }
        __syncthreads();
    }

#pragma unroll
    for (int i = 0; i < 4; i++) {
        int n = nbase + ty * 4 + i;
        if (n >= NN) continue;
#pragma unroll
        for (int j = 0; j < 4; j++) {
            int c = cbase + tx * 4 + j;
            if (c < NOUT) Y[(size_t)n * NOUT + c] = acc[i][j] + bias[c];
        }
    }
}

// ---------------- batchnorm stats / apply ----------------
__global__ void zero_stats_kernel() {
    int i = threadIdx.x;
    if (i < 2 * DD) g_stats[i] = 0.f;
}

__global__ void stats_kernel(const float* __restrict__ Y) {
    int col = threadIdx.x;  // 128 threads
    int r0 = blockIdx.x * 256;
    float s = 0.f, sq = 0.f;
    int rend = r0 + 256;
    if (rend > NN) rend = NN;
    for (int r = r0; r < rend; r++) {
        float v = Y[(size_t)r * DD + col];
        s += v;
        sq += v * v;
    }
    atomicAdd(&g_stats[col], s);
    atomicAdd(&g_stats[DD + col], sq);
}

__global__ void apply_kernel(float* __restrict__ Y, const float* __restrict__ g,
                             const float* __restrict__ b) {
    int idx = blockIdx.x * blockDim.x + threadIdx.x;  // one float4 per thread
    const int total4 = NN * DD / 4;
    if (idx >= total4) return;
    int col4 = (idx & (DD / 4 - 1)) * 4;
    float4 v = reinterpret_cast<float4*>(Y)[idx];
    float o[4] = {v.x, v.y, v.z, v.w};
#pragma unroll
    for (int q = 0; q < 4; q++) {
        int c = col4 + q;
        float mu = g_stats[c] * (1.0f / NN);
        float var = g_stats[DD + c] * (1.0f / NN) - mu * mu;
        float scale = rsqrtf(var + 1e-5f) * g[c];
        float shift = b[c] - mu * scale;
        o[q] = fmaxf(o[q] * scale + shift, 0.f);
    }
    v.x = o[0]; v.y = o[1]; v.z = o[2]; v.w = o[3];
    reinterpret_cast<float4*>(Y)[idx] = v;
}

// ---------------- log_softmax over 47 cols, warp per row ----------------
__global__ void lsm_kernel(float* __restrict__ O) {
    int row = blockIdx.x * 8 + (threadIdx.x >> 5);
    int lane = threadIdx.x & 31;
    if (row >= NN) return;
    float* p = O + (size_t)row * CC;
    float v0 = (lane < CC) ? p[lane] : -INFINITY;
    float v1 = (lane + 32 < CC) ? p[lane + 32] : -INFINITY;
    float m = fmaxf(v0, v1);
#pragma unroll
    for (int o = 16; o > 0; o >>= 1) m = fmaxf(m, __shfl_xor_sync(0xffffffffu, m, o));
    float s = ((lane < CC) ? expf(v0 - m) : 0.f) + ((lane + 32 < CC) ? expf(v1 - m) : 0.f);
#pragma unroll
    for (int o = 16; o > 0; o >>= 1) s += __shfl_xor_sync(0xffffffffu, s, o);
    float l = m + logf(s);
    if (lane < CC) p[lane] = v0 - l;
    if (lane + 32 < CC) p[lane + 32] = v1 - l;
}

// ---------------- launch ----------------
extern "C" void kernel_launch(void* const* d_in, const int* in_sizes, int n_in,
                              void* d_out, int out_size) {
    const float* x   = (const float*)d_in[0];
    const void*  ei  = d_in[1];
    const float* Wl0 = (const float*)d_in[2];
    const float* bl0 = (const float*)d_in[3];
    const float* Wr0 = (const float*)d_in[4];
    const float* g0  = (const float*)d_in[5];
    const float* be0 = (const float*)d_in[6];
    const float* Wl1 = (const float*)d_in[7];
    const float* bl1 = (const float*)d_in[8];
    const float* Wr1 = (const float*)d_in[9];
    const float* g1  = (const float*)d_in[10];
    const float* be1 = (const float*)d_in[11];
    const float* Wl2 = (const float*)d_in[12];
    const float* bl2 = (const float*)d_in[13];
    const float* Wr2 = (const float*)d_in[14];
    float* out = (float*)d_out;

    void* p;
    cudaGetSymbolAddress(&p, g_agg); float* aggp = (float*)p;
    cudaGetSymbolAddress(&p, g_b0);  float* b0p  = (float*)p;
    cudaGetSymbolAddress(&p, g_b1);  float* b1p  = (float*)p;

    // edge dtype probe + CSR build
    probe_kernel<<<1, 32>>>((const int*)ei);
    zero_deg_kernel<<<(NN + 255) / 256, 256>>>();
    deg_kernel<<<(EE + 255) / 256, 256>>>(ei);
    scan_kernel<<<1, 1024>>>();
    scatter_kernel<<<(EE + 255) / 256, 256>>>(ei);

    dim3 gemm_grid01(2, (NN + 63) / 64);
    dim3 gemm_grid2(1, (NN + 63) / 64);
    int agg_blocks = (NN * 32 + 255) / 256;
    int apply_blocks = (NN * DD / 4 + 255) / 256;
    int stats_blocks = (NN + 255) / 256;

    // layer 0
    agg_kernel<<<agg_blocks, 256>>>(x, aggp);
    gemm_kernel<128><<<gemm_grid01, 256>>>(aggp, x, Wl0, Wr0, bl0, b0p);
    zero_stats_kernel<<<1, 256>>>();
    stats_kernel<<<stats_blocks, 128>>>(b0p);
    apply_kernel<<<apply_blocks, 256>>>(b0p, g0, be0);

    // layer 1
    agg_kernel<<<agg_blocks, 256>>>(b0p, aggp);
    gemm_kernel<128><<<gemm_grid01, 256>>>(aggp, b0p, Wl1, Wr1, bl1, b1p);
    zero_stats_kernel<<<1, 256>>>();
    stats_kernel<<<stats_blocks, 128>>>(b1p);
    apply_kernel<<<apply_blocks, 256>>>(b1p, g1, be1);

    // layer 2 + log_softmax
    agg_kernel<<<agg_blocks, 256>>>(b1p, aggp);
    gemm_kernel<CC><<<gemm_grid2, 256>>>(aggp, b1p, Wl2, Wr2, bl2, out);
    lsm_kernel<<<(NN + 7) / 8, 256>>>(out);
}